// round 11
// baseline (speedup 1.0000x reference)
#include <cuda_runtime.h>
#include <cstdint>

// ---------------- problem constants ---------------------------------------
#define NB   64
#define CC   256
#define HH   28
#define WW   28
#define PIX  (HH*WW)                 // 784
#define NPIX (NB*PIX)                // 50176
#define TOT  (NB*CC*PIX)             // 12,845,056
#define NTILE 392                    // 28 h rows * 14 w-pairs

// smem geometry (u32 units); rows padded to 68 u32 (272B) for conflict-free
// fragment LDS (bank = (4*row + col) % 32, distinct across a frag's 8 rows x 4 cols)
#define APITCH 68
#define ASM_U32 (256*APITCH)         // 17408 u32 = 69,632 B
#define BSM_U32 (128*APITCH)         // 8704  u32 = 34,816 B
#define SMEM_BYTES ((ASM_U32 + BSM_U32)*4)   // 104,448 B

// ---------------- scratch (device globals) --------------------------------
__device__ int8_t   g_apad[900*64*256];            // s8 +-1 padded activations [posA][n][c]
__device__ int8_t   g_wq[2*9*256*256];             // s8 +-1 weights [which][tap][oc][ic]
__device__ float    g_xT[TOT];                     // x transposed to [pos*64+n][c]
__device__ float    g_out1T[TOT];                  // stage-1 output, same layout
__device__ short    g_yT[TOT];                     // conv output [row][oc]
__device__ int      g_p1[NTILE*CC], g_p2[NTILE*CC];
__device__ float    g_scale[2][CC], g_shift[2][CC];

// ---------------- IMMA: m16n8k32 s8 x s8 -> s32 ---------------------------
// PTX fragment order (row.col): a0=(row g, k-lo) a1=(row g+8, k-lo)
//                               a2=(row g, k-hi) a3=(row g+8, k-hi)
__device__ __forceinline__ void imma16832(int* d, uint32_t a0, uint32_t a1,
                                          uint32_t a2, uint32_t a3,
                                          uint32_t b0, uint32_t b1) {
    asm volatile(
        "mma.sync.aligned.m16n8k32.row.col.s32.s8.s8.s32 "
        "{%0,%1,%2,%3}, {%4,%5,%6,%7}, {%8,%9}, {%0,%1,%2,%3};"
        : "+r"(d[0]), "+r"(d[1]), "+r"(d[2]), "+r"(d[3])
        : "r"(a0), "r"(a1), "r"(a2), "r"(a3), "r"(b0), "r"(b1));
}

// ---------------- zero the padded activation buffer -----------------------
__global__ void zero_apad_kernel() {
    int i = blockIdx.x * 256 + threadIdx.x;          // 921600 uint4
    ((uint4*)g_apad)[i] = make_uint4(0, 0, 0, 0);
}

// ---------------- pack weights to s8 +-1 -----------------------------------
// g_wq layout: [which][tap][oc][ic]
__global__ void pack_wq_kernel(const float* __restrict__ w1,
                               const float* __restrict__ w2) {
    int oc = blockIdx.x, which = blockIdx.y, ic = threadIdx.x;
    const float* w = which ? w2 : w1;
    #pragma unroll
    for (int tap = 0; tap < 9; tap++) {
        float v = w[oc*2304 + ic*9 + tap];
        g_wq[(((size_t)which*9 + tap)*256 + oc)*256 + ic] = (v > 0.0f) ? 1 : -1;
    }
}

// ---------------- x NCHW -> xT [pos][n][c] + Apad s8 signs ----------------
__global__ void transpose_in_kernel(const float* __restrict__ x) {
    int h = blockIdx.x, n = blockIdx.y, c = threadIdx.x;
    const float* src = x + ((size_t)(n*CC + c))*PIX + h*WW;
    float4 v4[7];
    #pragma unroll
    for (int q = 0; q < 7; q++) v4[q] = ((const float4*)src)[q];
    const float* v = (const float*)v4;
    #pragma unroll
    for (int w = 0; w < 28; w++) {
        float f = v[w];
        size_t row = (size_t)(h*WW + w)*64 + n;
        g_xT[row*CC + c] = f;
        size_t posA = (size_t)((h+1)*30 + (w+1));
        g_apad[(posA*64 + n)*CC + c] = (f > 0.0f) ? 1 : -1;
    }
}

// ---------------- IMMA implicit-GEMM binary conv --------------------------
// grid = 392 tiles. Tile: M=128 rows (2 pixel positions x 64 batch) x N=256 oc
// (2 passes of 128). K = 9 taps x 256 ch. A cluster = 4 padded positions
// (256 rows x 256B); tap (dy,dx) -> A row shift of dx*64.
__global__ void __launch_bounds__(256) conv_mma_kernel(int which) {
    extern __shared__ __align__(16) uint32_t sm[];
    uint32_t* As = sm;                 // [256][APITCH]
    uint32_t* Bs = sm + ASM_U32;       // [128][APITCH]
    __shared__ int s_p1[4][256], s_p2[4][256];

    const int tid  = threadIdx.x;
    const int lane = tid & 31;
    const int g    = lane >> 2;         // groupID (row in fragment)
    const int tig  = lane & 3;          // thread-in-group (k / col)
    const int warp = tid >> 5;
    const int mg   = warp >> 1;         // 0..3: M slice (32 rows)
    const int ng   = warp & 1;          // 0..1: N slice (64 cols)

    const int b  = blockIdx.x;
    const int h  = b / 14, wp = b - h*14;

    for (int pass = 0; pass < 2; pass++) {
        int acc[2][8][4];
        #pragma unroll
        for (int mf = 0; mf < 2; mf++)
            #pragma unroll
            for (int nf = 0; nf < 8; nf++)
                #pragma unroll
                for (int q = 0; q < 4; q++) acc[mf][nf][q] = 0;

        for (int dy = 0; dy < 3; dy++) {
            for (int dx = 0; dx < 3; dx++) {
                __syncthreads();     // prior use of As/Bs complete
                if (dx == 0) {
                    // A cluster: padded positions (h+dy)*30 + wp*2 .. +3
                    const uint4* asrc = (const uint4*)(g_apad +
                        ((size_t)((h+dy)*30 + wp*2)*64)*256);
                    #pragma unroll
                    for (int t = 0; t < 16; t++) {
                        int i = tid + t*256;          // 4096 uint4
                        int row = i >> 4, cu = i & 15;
                        *(uint4*)&As[row*APITCH + cu*4] = asrc[i];
                    }
                }
                {   // B panel: tap (dy,dx), oc slice [pass*128, +128)
                    const uint4* bsrc = (const uint4*)(g_wq +
                        (((size_t)which*9 + dy*3 + dx)*256 + pass*128)*256);
                    #pragma unroll
                    for (int t = 0; t < 8; t++) {
                        int i = tid + t*256;          // 2048 uint4
                        int row = i >> 4, cu = i & 15;
                        *(uint4*)&Bs[row*APITCH + cu*4] = bsrc[i];
                    }
                }
                __syncthreads();

                const int abase = dx*64;
                #pragma unroll
                for (int step = 0; step < 8; step++) {
                    uint32_t bf[8][2];
                    #pragma unroll
                    for (int nf = 0; nf < 8; nf++) {
                        int brow = ng*64 + nf*8 + g;
                        bf[nf][0] = Bs[brow*APITCH + step*8 + tig];
                        bf[nf][1] = Bs[brow*APITCH + step*8 + tig + 4];
                    }
                    #pragma unroll
                    for (int mf = 0; mf < 2; mf++) {
                        int arow = abase + mg*32 + mf*16 + g;
                        uint32_t a0 = As[arow*APITCH + step*8 + tig];          // row g,   k-lo
                        uint32_t a1 = As[(arow+8)*APITCH + step*8 + tig];      // row g+8, k-lo
                        uint32_t a2 = As[arow*APITCH + step*8 + tig + 4];      // row g,   k-hi
                        uint32_t a3 = As[(arow+8)*APITCH + step*8 + tig + 4];  // row g+8, k-hi
                        #pragma unroll
                        for (int nf = 0; nf < 8; nf++)
                            imma16832(acc[mf][nf], a0, a1, a2, a3,
                                      bf[nf][0], bf[nf][1]);
                    }
                }
            }
        }

        // ---- epilogue for this n-chunk: store y + per-column partial sums
        #pragma unroll
        for (int mf = 0; mf < 2; mf++) {
            int r0 = mg*32 + mf*16 + g;
            #pragma unroll
            for (int nf = 0; nf < 8; nf++) {
                int col = pass*128 + ng*64 + nf*8 + tig*2;
                short2 v0, v1;
                v0.x = (short)acc[mf][nf][0]; v0.y = (short)acc[mf][nf][1];
                v1.x = (short)acc[mf][nf][2]; v1.y = (short)acc[mf][nf][3];
                *(short2*)(g_yT + ((size_t)b*128 + r0)*256 + col)     = v0;
                *(short2*)(g_yT + ((size_t)b*128 + r0 + 8)*256 + col) = v1;
            }
        }
        #pragma unroll
        for (int nf = 0; nf < 8; nf++) {
            int s1A = 0, s2A = 0, s1B = 0, s2B = 0;
            #pragma unroll
            for (int mf = 0; mf < 2; mf++) {
                int c0 = acc[mf][nf][0], c1 = acc[mf][nf][1];
                int c2 = acc[mf][nf][2], c3 = acc[mf][nf][3];
                s1A += c0 + c2;  s2A += c0*c0 + c2*c2;
                s1B += c1 + c3;  s2B += c1*c1 + c3*c3;
            }
            #pragma unroll
            for (int o = 4; o <= 16; o <<= 1) {      // reduce over g lanes
                s1A += __shfl_xor_sync(0xffffffffu, s1A, o);
                s2A += __shfl_xor_sync(0xffffffffu, s2A, o);
                s1B += __shfl_xor_sync(0xffffffffu, s1B, o);
                s2B += __shfl_xor_sync(0xffffffffu, s2B, o);
            }
            if (g == 0) {
                int col = pass*128 + ng*64 + nf*8 + tig*2;
                s_p1[mg][col] = s1A;  s_p1[mg][col+1] = s1B;
                s_p2[mg][col] = s2A;  s_p2[mg][col+1] = s2B;
            }
        }
    }

    __syncthreads();
    if (tid < 256) {
        g_p1[b*256 + tid] = s_p1[0][tid] + s_p1[1][tid] + s_p1[2][tid] + s_p1[3][tid];
        g_p2[b*256 + tid] = s_p2[0][tid] + s_p2[1][tid] + s_p2[2][tid] + s_p2[3][tid];
    }
}

// ---------------- finalize BN stats from per-tile partials -----------------
__global__ void __launch_bounds__(128) finalize_kernel(int which,
                                                       const float* __restrict__ gamma,
                                                       const float* __restrict__ beta) {
    const int oc = blockIdx.x;
    long long s1 = 0, s2 = 0;
    for (int i = threadIdx.x; i < NTILE; i += 128) {
        s1 += g_p1[i*256 + oc];
        s2 += g_p2[i*256 + oc];
    }
    #pragma unroll
    for (int o = 16; o; o >>= 1) {
        s1 += __shfl_down_sync(0xffffffffu, s1, o);
        s2 += __shfl_down_sync(0xffffffffu, s2, o);
    }
    __shared__ long long a1[4], a2[4];
    int w = threadIdx.x >> 5, l = threadIdx.x & 31;
    if (l == 0) { a1[w] = s1; a2[w] = s2; }
    __syncthreads();
    if (threadIdx.x == 0) {
        long long t1 = a1[0]+a1[1]+a1[2]+a1[3], t2 = a2[0]+a2[1]+a2[2]+a2[3];
        double m   = (double)t1 / (double)NPIX;
        double ex2 = (double)t2 / (double)NPIX;
        double inv = rsqrt(ex2 - m*m + 1e-5);
        double gs  = (double)gamma[oc] * inv;
        g_scale[which][oc] = (float)gs;
        g_shift[which][oc] = (float)((double)beta[oc] - m*gs);
    }
}

// ---------------- stage-1 BN + residual + clip + stage-2 signs ------------
__global__ void __launch_bounds__(256) bnres1_kernel() {
    int idx4 = blockIdx.x * 256 + threadIdx.x;     // TOT/4 elements
    int c4 = idx4 & 63;
    int row = idx4 >> 6;
    short4 y = ((const short4*)g_yT)[idx4];
    float4 sc = *(const float4*)&g_scale[0][c4*4];
    float4 sf = *(const float4*)&g_shift[0][c4*4];
    float4 r  = ((const float4*)g_xT)[idx4];
    float4 o;
    o.x = fminf(1.f, fmaxf(-1.f, fmaf((float)y.x, sc.x, sf.x) + r.x));
    o.y = fminf(1.f, fmaxf(-1.f, fmaf((float)y.y, sc.y, sf.y) + r.y));
    o.z = fminf(1.f, fmaxf(-1.f, fmaf((float)y.z, sc.z, sf.z) + r.z));
    o.w = fminf(1.f, fmaxf(-1.f, fmaf((float)y.w, sc.w, sf.w) + r.w));
    ((float4*)g_out1T)[idx4] = o;
    char4 s;
    s.x = (o.x > 0.f) ? 1 : -1;
    s.y = (o.y > 0.f) ? 1 : -1;
    s.z = (o.z > 0.f) ? 1 : -1;
    s.w = (o.w > 0.f) ? 1 : -1;
    int pos = row >> 6, n = row & 63;
    int hh = pos / 28, ww = pos - hh*28;
    size_t posA = (size_t)((hh+1)*30 + (ww+1));
    ((char4*)g_apad)[((posA*64 + n)*256 + c4*4) >> 2] = s;
}

// ---------------- stage-2 BN + residual + clip + transpose out ------------
__global__ void bnres2_kernel(float* __restrict__ out) {
    int h = blockIdx.x, n = blockIdx.y, c = threadIdx.x;
    float sc = g_scale[1][c], sf = g_shift[1][c];
    float4 v4[7];
    float* v = (float*)v4;
    #pragma unroll
    for (int w = 0; w < 28; w++) {
        size_t row = (size_t)(h*WW + w)*64 + n;
        float y  = (float)g_yT[row*CC + c];
        float o1 = g_out1T[row*CC + c];
        v[w] = fminf(1.f, fmaxf(-1.f, fmaf(y, sc, sf) + o1));
    }
    float* dst = out + ((size_t)(n*CC + c))*PIX + h*WW;
    #pragma unroll
    for (int q = 0; q < 7; q++) ((float4*)dst)[q] = v4[q];
}

// ---------------- launcher -------------------------------------------------
extern "C" void kernel_launch(void* const* d_in, const int* in_sizes, int n_in,
                              void* d_out, int out_size) {
    const float* x      = (const float*)d_in[0];
    const float* w1     = (const float*)d_in[1];
    const float* gamma1 = (const float*)d_in[2];
    const float* beta1  = (const float*)d_in[3];
    const float* w2     = (const float*)d_in[4];
    const float* gamma2 = (const float*)d_in[5];
    const float* beta2  = (const float*)d_in[6];
    float* out = (float*)d_out;

    cudaFuncSetAttribute(conv_mma_kernel,
                         cudaFuncAttributeMaxDynamicSharedMemorySize, SMEM_BYTES);

    zero_apad_kernel<<<3600, 256>>>();               // 900*64*256 B
    pack_wq_kernel<<<dim3(CC, 2), 256>>>(w1, w2);
    transpose_in_kernel<<<dim3(HH, NB), 256>>>(x);

    // stage 1
    conv_mma_kernel<<<NTILE, 256, SMEM_BYTES>>>(0);
    finalize_kernel<<<CC, 128>>>(0, gamma1, beta1);
    bnres1_kernel<<<TOT/1024, 256>>>();

    // stage 2
    conv_mma_kernel<<<NTILE, 256, SMEM_BYTES>>>(1);
    finalize_kernel<<<CC, 128>>>(1, gamma2, beta2);
    bnres2_kernel<<<dim3(HH, NB), 256>>>(out);
}

// round 12
// speedup vs baseline: 2.2414x; 2.2414x over previous
#include <cuda_runtime.h>
#include <cstdint>

// Problem constants
#define NB   64
#define CC   256
#define HH   28
#define WW   28
#define PIX  (HH*WW)                 // 784
#define NPIX (NB*PIX)                // 50176
#define TOT  (NB*CC*PIX)             // 12,845,056
#define CW   8                       // 256 channels / 32 bits
#define TH   4                       // rows per conv block
#define OCCH 32                      // output channels per block
#define NCH  (CC/OCCH)               // 8 chunks
#define NG   (OCCH/4)                // 8 groups of 4 ocs

// ---------------- scratch (device globals) ---------------------------------
__device__ uint32_t g_bits[NB*PIX*CW];            // packed activation signs
__device__ uint32_t g_wb[2][CC*72];               // packed weight signs
__device__ int      g_pw[2][CC*9];                // popcount of each weight tap
__device__ short    g_y[TOT];                     // integer conv output (NCHW)
__device__ float    g_out1[TOT];                  // stage-1 output (NCHW)
__device__ float    g_scale[2][CC], g_shift[2][CC];

// ---------------- pack weights: sign bits + per-tap popcounts -------------
__global__ void pack_w_kernel(const float* __restrict__ w1,
                              const float* __restrict__ w2) {
    int oc    = blockIdx.x;
    int which = blockIdx.y;
    const float* w = which ? w2 : w1;
    int tap  = threadIdx.y;          // 0..8
    int lane = threadIdx.x;          // 0..31
    int pwt = 0;
    #pragma unroll
    for (int j = 0; j < CW; j++) {
        float v = w[oc*2304 + (j*32 + lane)*9 + tap];
        unsigned word = __ballot_sync(0xffffffffu, v > 0.0f);
        if (lane == 0) g_wb[which][oc*72 + tap*8 + j] = word;
        pwt += __popc(word);
    }
    if (lane == 0) g_pw[which][oc*9 + tap] = pwt;
}

// ---------------- pack x signs (stage 1) ------------------------------------
__global__ void pack_sign_kernel(const float* __restrict__ src) {
    __shared__ unsigned char s[CC*WW];      // 7168 sign bytes
    int h = blockIdx.x, n = blockIdx.y;
    int basen = n * (CC*PIX);
    #pragma unroll
    for (int k = 0; k < 28; k++) {
        int e = threadIdx.x + k*256;         // e = c*28 + w
        int c = e / 28, w = e - c*28;
        float v = src[basen + c*PIX + h*WW + w];
        s[e] = (v > 0.0f) ? 1 : 0;
    }
    __syncthreads();
    int warp = threadIdx.x >> 5, lane = threadIdx.x & 31;
    #pragma unroll
    for (int w = 0; w < 28; w++) {
        unsigned pred = s[(warp*32 + lane)*28 + w];
        unsigned word = __ballot_sync(0xffffffffu, pred != 0);
        if (lane == w) g_bits[n*(PIX*CW) + (h*WW + w)*CW + warp] = word;
    }
}

// ---------------- XNOR conv via two-level CSA popcount ---------------------
// Per (oc, tap): 8 XOR words -> 3 FAs -> (S, v7 w1; cA,cB,C w2), then a
// running `ones` accumulator FA(ones,S,v7) converts the two w1 popcs into one
// w2 popc. popc/oc = 9*4 + 1 = 37; alu ~ balanced with popc pipe.
#define SMEM_W_U32  (OCCH*72)                 // 2304  [g][tap][o][j]
#define SMEM_A_U32  (6*2*32*4)                // 1536  [row][half][col][k]
#define SMEM_ADJ    (OCCH*9)                  // 288
#define SMEM_U32    (SMEM_W_U32 + SMEM_A_U32 + SMEM_ADJ)

#define FA(x, y, z, s, c)  { uint32_t _x=(x), _y=(y), _z=(z); \
                             (s) = _x^_y^_z; (c) = (_x&_y) | (_z&(_x|_y)); }

#define TAP_OC(WL, WH, ones, a2) { \
    uint32_t v0=AL.x^(WL).x, v1=AL.y^(WL).y, v2=AL.z^(WL).z, v3=AL.w^(WL).w; \
    uint32_t v4=AH.x^(WH).x, v5=AH.y^(WH).y, v6=AH.z^(WH).z, v7=AH.w^(WH).w; \
    uint32_t sA,cA,sB,cB,S,C,c1; \
    FA(v0,v1,v2,sA,cA); FA(v3,v4,v5,sB,cB); FA(sA,sB,v6,S,C); \
    FA(ones,S,v7,ones,c1); \
    a2 += (__popc(cA)+__popc(cB)) + (__popc(C)+__popc(c1)); }

__global__ void __launch_bounds__(128, 6) conv_kernel(int which) {
    extern __shared__ uint32_t sh[];
    uint32_t* s_w  = sh;                              // [g][tap][o][j0..7]
    uint32_t* s_a  = sh + SMEM_W_U32;                 // [row][half][col][k]
    int*      s_adj = (int*)(sh + SMEM_W_U32 + SMEM_A_U32);

    const int n   = blockIdx.y;
    const int h0  = blockIdx.x * TH;
    const int oc0 = blockIdx.z * OCCH;
    const int tid = threadIdx.x;

    const uint32_t* wb = g_wb[which];
    for (int i = tid; i < SMEM_W_U32; i += 128) {
        int j   = i & 7;
        int o   = (i >> 3) & 3;
        int rem = i % 288;
        int tap = rem >> 5;
        int g   = i / 288;
        s_w[i] = wb[(oc0 + g*4 + o)*72 + tap*8 + j];
    }
    for (int i = tid; i < SMEM_A_U32; i += 128) {
        int k    = i & 3;
        int col  = (i >> 2) & 31;
        int half = (i >> 7) & 1;
        int row  = i >> 8;
        int hh   = h0 - 1 + row;
        int wo   = col - 1;
        uint32_t v = 0;
        if (hh >= 0 && hh < HH && wo >= 0 && wo < WW)
            v = g_bits[n*(PIX*CW) + (hh*WW + wo)*CW + half*4 + k];
        s_a[i] = v;
    }
    const int* pw = g_pw[which] + oc0*9;
    for (int e = tid; e < SMEM_ADJ; e += 128) {
        int ocl = e / 9, combo = e - ocl*9;
        int rs = combo / 3, cs = combo - rs*3;
        const int* pwo = pw + ocl*9;
        int corr = 0;
        if (rs) { int ir = (rs == 1) ? 0 : 2;
                  corr += pwo[ir*3] + pwo[ir*3+1] + pwo[ir*3+2]; }
        if (cs) { int ic = (cs == 1) ? 0 : 2;
                  corr += pwo[ic] + pwo[3+ic] + pwo[6+ic]; }
        if (rs && cs) { int ir = (rs == 1) ? 0 : 2, ic = (cs == 1) ? 0 : 2;
                        corr -= pwo[ir*3 + ic]; }
        int nv = (rs ? 2 : 3) * (cs ? 2 : 3);
        s_adj[e] = CC*nv + 2*corr;
    }
    __syncthreads();

    if (tid >= TH*WW) return;          // 112 workers

    const int r = tid / WW;
    const int w = tid - r*WW;
    const int h = h0 + r;
    const int rs = (h == 0) ? 1 : ((h == HH-1) ? 2 : 0);
    const int cs = (w == 0) ? 1 : ((w == WW-1) ? 2 : 0);
    const int combo = rs*3 + cs;

    short* yout = g_y + (size_t)n*(CC*PIX) + (size_t)oc0*PIX + h0*WW + tid;

    for (int g = 0; g < NG; g++) {
        uint32_t on0 = 0, on1 = 0, on2 = 0, on3 = 0;
        int a2_0 = 0, a2_1 = 0, a2_2 = 0, a2_3 = 0;
        const uint4* wq = (const uint4*)s_w + g*72;
        #pragma unroll
        for (int ky = 0; ky < 3; ky++) {
            const uint4* apL = (const uint4*)s_a + (((r + ky)*2 + 0)*32 + w);
            const uint4* apH = (const uint4*)s_a + (((r + ky)*2 + 1)*32 + w);
            uint4 L0 = apL[0], L1 = apL[1], L2 = apL[2];
            uint4 H0 = apH[0], H1 = apH[1], H2 = apH[2];
            #pragma unroll
            for (int kx = 0; kx < 3; kx++) {
                uint4 AL = (kx == 0) ? L0 : ((kx == 1) ? L1 : L2);
                uint4 AH = (kx == 0) ? H0 : ((kx == 1) ? H1 : H2);
                const uint4* wt = wq + (ky*3 + kx)*8;
                uint4 WL, WH;
                WL = wt[0]; WH = wt[1]; TAP_OC(WL, WH, on0, a2_0);
                WL = wt[2]; WH = wt[3]; TAP_OC(WL, WH, on1, a2_1);
                WL = wt[4]; WH = wt[5]; TAP_OC(WL, WH, on2, a2_2);
                WL = wt[6]; WH = wt[7]; TAP_OC(WL, WH, on3, a2_3);
            }
        }
        const int* adj = s_adj + (g*4)*9 + combo;
        yout[(g*4 + 0)*PIX] = (short)(adj[0]  - 2*(__popc(on0) + 2*a2_0));
        yout[(g*4 + 1)*PIX] = (short)(adj[9]  - 2*(__popc(on1) + 2*a2_1));
        yout[(g*4 + 2)*PIX] = (short)(adj[18] - 2*(__popc(on2) + 2*a2_2));
        yout[(g*4 + 3)*PIX] = (short)(adj[27] - 2*(__popc(on3) + 2*a2_3));
    }
}

// ---------------- per-channel stats -> scale/shift (no atomics) ------------
__global__ void __launch_bounds__(512) chanstats_kernel(int which,
                                                        const float* __restrict__ gamma,
                                                        const float* __restrict__ beta) {
    const int oc = blockIdx.x;
    int s1 = 0, s2 = 0;     // per-thread <=25 short4: s2 <= 531M < 2^31
    for (int i = threadIdx.x; i < NB*196; i += 512) {
        int nn = i / 196, j = i - nn*196;
        short4 v = ((const short4*)(g_y + ((size_t)(nn*CC + oc))*PIX))[j];
        int a = v.x, b = v.y, c = v.z, d = v.w;
        s1 += (a + b) + (c + d);
        s2 += (a*a + b*b) + (c*c + d*d);
    }
    long long l1 = s1, l2 = s2;
    #pragma unroll
    for (int o = 16; o; o >>= 1) {
        l1 += __shfl_down_sync(0xffffffffu, l1, o);
        l2 += __shfl_down_sync(0xffffffffu, l2, o);
    }
    __shared__ long long sh1[16], sh2[16];
    int warp = threadIdx.x >> 5, lane = threadIdx.x & 31;
    if (lane == 0) { sh1[warp] = l1; sh2[warp] = l2; }
    __syncthreads();
    if (threadIdx.x == 0) {
        long long t1 = 0, t2 = 0;
        #pragma unroll
        for (int k = 0; k < 16; k++) { t1 += sh1[k]; t2 += sh2[k]; }
        double m   = (double)t1 / (double)NPIX;
        double ex2 = (double)t2 / (double)NPIX;
        double var = ex2 - m*m;
        double inv = rsqrt(var + 1e-5);
        double gs  = (double)gamma[oc] * inv;
        g_scale[which][oc] = (float)gs;
        g_shift[which][oc] = (float)((double)beta[oc] - m * gs);
    }
}

// ---------------- stage-1 BN + residual + clip, fused sign-pack ------------
// block (h, n); 256 threads = channels. Writes out1 (NCHW) and the packed
// stage-2 sign bits directly (replaces the second pack_sign pass).
__global__ void __launch_bounds__(256) bnres1_pack_kernel(const float* __restrict__ x) {
    __shared__ unsigned char s[CC*WW];
    int h = blockIdx.x, n = blockIdx.y, c = threadIdx.x;
    float sc = g_scale[0][c], sf = g_shift[0][c];
    size_t base = ((size_t)(n*CC + c))*PIX + h*WW;
    const short4* yp = (const short4*)(g_y + base);
    const float4* xp = (const float4*)(x + base);
    float4* op = (float4*)(g_out1 + base);
    #pragma unroll
    for (int q = 0; q < 7; q++) {
        short4 y4 = yp[q];
        float4 x4 = xp[q];
        float4 o;
        o.x = fminf(1.f, fmaxf(-1.f, fmaf((float)y4.x, sc, sf) + x4.x));
        o.y = fminf(1.f, fmaxf(-1.f, fmaf((float)y4.y, sc, sf) + x4.y));
        o.z = fminf(1.f, fmaxf(-1.f, fmaf((float)y4.z, sc, sf) + x4.z));
        o.w = fminf(1.f, fmaxf(-1.f, fmaf((float)y4.w, sc, sf) + x4.w));
        op[q] = o;
        s[c*28 + q*4 + 0] = (o.x > 0.f) ? 1 : 0;
        s[c*28 + q*4 + 1] = (o.y > 0.f) ? 1 : 0;
        s[c*28 + q*4 + 2] = (o.z > 0.f) ? 1 : 0;
        s[c*28 + q*4 + 3] = (o.w > 0.f) ? 1 : 0;
    }
    __syncthreads();
    int warp = c >> 5, lane = c & 31;
    #pragma unroll
    for (int w = 0; w < 28; w++) {
        unsigned pred = s[(warp*32 + lane)*28 + w];
        unsigned word = __ballot_sync(0xffffffffu, pred != 0);
        if (lane == w) g_bits[n*(PIX*CW) + (h*WW + w)*CW + warp] = word;
    }
}

// ---------------- stage-2 BN + residual + clip (vectorized) ----------------
__global__ void __launch_bounds__(256) bnres2_kernel(float* __restrict__ dst_out) {
    int idx4 = blockIdx.x * 256 + threadIdx.x;     // grid = TOT/1024
    int base = idx4 << 2;
    int c = (base / PIX) & (CC - 1);
    float sc = g_scale[1][c], sf = g_shift[1][c];
    short4 yv = ((const short4*)g_y)[idx4];
    float4 rv = ((const float4*)g_out1)[idx4];
    float4 o;
    o.x = fminf(1.0f, fmaxf(-1.0f, fmaf((float)yv.x, sc, sf) + rv.x));
    o.y = fminf(1.0f, fmaxf(-1.0f, fmaf((float)yv.y, sc, sf) + rv.y));
    o.z = fminf(1.0f, fmaxf(-1.0f, fmaf((float)yv.z, sc, sf) + rv.z));
    o.w = fminf(1.0f, fmaxf(-1.0f, fmaf((float)yv.w, sc, sf) + rv.w));
    ((float4*)dst_out)[idx4] = o;
}

// ---------------- launcher -------------------------------------------------
extern "C" void kernel_launch(void* const* d_in, const int* in_sizes, int n_in,
                              void* d_out, int out_size) {
    const float* x      = (const float*)d_in[0];
    const float* w1     = (const float*)d_in[1];
    const float* gamma1 = (const float*)d_in[2];
    const float* beta1  = (const float*)d_in[3];
    const float* w2     = (const float*)d_in[4];
    const float* gamma2 = (const float*)d_in[5];
    const float* beta2  = (const float*)d_in[6];
    float* out = (float*)d_out;

    constexpr int SMEM_BYTES = SMEM_U32 * 4;       // 16,512 B

    pack_w_kernel<<<dim3(CC, 2), dim3(32, 9)>>>(w1, w2);

    // stage 1
    pack_sign_kernel<<<dim3(HH, NB), 256>>>(x);
    conv_kernel<<<dim3(HH/TH, NB, NCH), 128, SMEM_BYTES>>>(0);
    chanstats_kernel<<<CC, 512>>>(0, gamma1, beta1);
    bnres1_pack_kernel<<<dim3(HH, NB), 256>>>(x);   // out1 + stage-2 sign bits

    // stage 2
    conv_kernel<<<dim3(HH/TH, NB, NCH), 128, SMEM_BYTES>>>(1);
    chanstats_kernel<<<CC, 512>>>(1, gamma2, beta2);
    bnres2_kernel<<<TOT/1024, 256>>>(out);
}

// round 13
// speedup vs baseline: 2.2912x; 1.0222x over previous
#include <cuda_runtime.h>
#include <cstdint>

// Problem constants
#define NB   64
#define CC   256
#define HH   28
#define WW   28
#define PIX  (HH*WW)                 // 784
#define NPIX (NB*PIX)                // 50176
#define TOT  (NB*CC*PIX)             // 12,845,056
#define CW   8                       // 256 channels / 32 bits
#define TH   4                       // rows per conv block
#define OCCH 32                      // output channels per block
#define NCH  (CC/OCCH)               // 8 chunks
#define NG   (OCCH/4)                // 8 groups of 4 ocs

// ---------------- scratch (device globals) ---------------------------------
__device__ uint32_t g_bits[NB*PIX*CW];            // packed activation signs
__device__ uint32_t g_wb[2][CC*72];               // packed weight signs
__device__ int      g_pw[2][CC*9];                // popcount of each weight tap
__device__ short    g_y[TOT];                     // integer conv output (NCHW)
__device__ float    g_out1[TOT];                  // stage-1 output (NCHW)
__device__ float    g_scale[2][CC], g_shift[2][CC];

// ---------------- pack weights: sign bits + per-tap popcounts -------------
__global__ void pack_w_kernel(const float* __restrict__ w1,
                              const float* __restrict__ w2) {
    int oc    = blockIdx.x;
    int which = blockIdx.y;
    const float* w = which ? w2 : w1;
    int tap  = threadIdx.y;          // 0..8
    int lane = threadIdx.x;          // 0..31
    int pwt = 0;
    #pragma unroll
    for (int j = 0; j < CW; j++) {
        float v = w[oc*2304 + (j*32 + lane)*9 + tap];
        unsigned word = __ballot_sync(0xffffffffu, v > 0.0f);
        if (lane == 0) g_wb[which][oc*72 + tap*8 + j] = word;
        pwt += __popc(word);
    }
    if (lane == 0) g_pw[which][oc*9 + tap] = pwt;
}

// ---------------- pack x signs (stage 1) ------------------------------------
__global__ void pack_sign_kernel(const float* __restrict__ src) {
    __shared__ unsigned char s[CC*WW];      // 7168 sign bytes
    int h = blockIdx.x, n = blockIdx.y;
    int basen = n * (CC*PIX);
    #pragma unroll
    for (int k = 0; k < 28; k++) {
        int e = threadIdx.x + k*256;         // e = c*28 + w
        int c = e / 28, w = e - c*28;
        float v = src[basen + c*PIX + h*WW + w];
        s[e] = (v > 0.0f) ? 1 : 0;
    }
    __syncthreads();
    int warp = threadIdx.x >> 5, lane = threadIdx.x & 31;
    #pragma unroll
    for (int w = 0; w < 28; w++) {
        unsigned pred = s[(warp*32 + lane)*28 + w];
        unsigned word = __ballot_sync(0xffffffffu, pred != 0);
        if (lane == w) g_bits[n*(PIX*CW) + (h*WW + w)*CW + warp] = word;
    }
}

// ---------------- XNOR conv via CSA-compressed popcount (R8 version) ------
// Per (oc, tap): 8 XOR words compressed by 3 full adders into 5 popc words
// (weights 1,1 and 2,2,2) — balanced alu vs quarter-rate popc pipes.
#define SMEM_W_U32  (OCCH*72)                 // 2304  [g][tap][o][j]
#define SMEM_A_U32  (6*2*32*4)                // 1536  [row][half][col][k]
#define SMEM_ADJ    (OCCH*9)                  // 288
#define SMEM_U32    (SMEM_W_U32 + SMEM_A_U32 + SMEM_ADJ)

#define FA(x, y, z, s, c)  { s = (x)^(y)^(z); c = ((x)&(y)) | ((z)&((x)|(y))); }

__global__ void __launch_bounds__(128, 6) conv_kernel(int which) {
    extern __shared__ uint32_t sh[];
    uint32_t* s_w  = sh;                              // [g][tap][o][j0..7]
    uint32_t* s_a  = sh + SMEM_W_U32;                 // [row][half][col][k]
    int*      s_adj = (int*)(sh + SMEM_W_U32 + SMEM_A_U32);

    const int n   = blockIdx.y;
    const int h0  = blockIdx.x * TH;
    const int oc0 = blockIdx.z * OCCH;
    const int tid = threadIdx.x;

    const uint32_t* wb = g_wb[which];
    for (int i = tid; i < SMEM_W_U32; i += 128) {
        int j   = i & 7;
        int o   = (i >> 3) & 3;
        int rem = i % 288;
        int tap = rem >> 5;
        int g   = i / 288;
        s_w[i] = wb[(oc0 + g*4 + o)*72 + tap*8 + j];
    }
    for (int i = tid; i < SMEM_A_U32; i += 128) {
        int k    = i & 3;
        int col  = (i >> 2) & 31;
        int half = (i >> 7) & 1;
        int row  = i >> 8;
        int hh   = h0 - 1 + row;
        int wo   = col - 1;
        uint32_t v = 0;
        if (hh >= 0 && hh < HH && wo >= 0 && wo < WW)
            v = g_bits[n*(PIX*CW) + (hh*WW + wo)*CW + half*4 + k];
        s_a[i] = v;
    }
    const int* pw = g_pw[which] + oc0*9;
    for (int e = tid; e < SMEM_ADJ; e += 128) {
        int ocl = e / 9, combo = e - ocl*9;
        int rs = combo / 3, cs = combo - rs*3;
        const int* pwo = pw + ocl*9;
        int corr = 0;
        if (rs) { int ir = (rs == 1) ? 0 : 2;
                  corr += pwo[ir*3] + pwo[ir*3+1] + pwo[ir*3+2]; }
        if (cs) { int ic = (cs == 1) ? 0 : 2;
                  corr += pwo[ic] + pwo[3+ic] + pwo[6+ic]; }
        if (rs && cs) { int ir = (rs == 1) ? 0 : 2, ic = (cs == 1) ? 0 : 2;
                        corr -= pwo[ir*3 + ic]; }
        int nv = (rs ? 2 : 3) * (cs ? 2 : 3);
        s_adj[e] = CC*nv + 2*corr;
    }
    __syncthreads();

    if (tid >= TH*WW) return;          // 112 workers

    const int r = tid / WW;
    const int w = tid - r*WW;
    const int h = h0 + r;
    const int rs = (h == 0) ? 1 : ((h == HH-1) ? 2 : 0);
    const int cs = (w == 0) ? 1 : ((w == WW-1) ? 2 : 0);
    const int combo = rs*3 + cs;

    short* yout = g_y + (size_t)n*(CC*PIX) + (size_t)oc0*PIX + h0*WW + tid;

    for (int g = 0; g < NG; g++) {
        int acc1_0 = 0, acc1_1 = 0, acc1_2 = 0, acc1_3 = 0;   // weight-1 popcs
        int acc2_0 = 0, acc2_1 = 0, acc2_2 = 0, acc2_3 = 0;   // weight-2 popcs
        const uint4* wq = (const uint4*)s_w + g*72;            // [tap][o][lo/hi]
        #pragma unroll
        for (int ky = 0; ky < 3; ky++) {
            const uint4* apL = (const uint4*)s_a + (((r + ky)*2 + 0)*32 + w);
            const uint4* apH = (const uint4*)s_a + (((r + ky)*2 + 1)*32 + w);
            uint4 L0 = apL[0], L1 = apL[1], L2 = apL[2];
            uint4 H0 = apH[0], H1 = apH[1], H2 = apH[2];
            #pragma unroll
            for (int kx = 0; kx < 3; kx++) {
                uint4 AL = (kx == 0) ? L0 : ((kx == 1) ? L1 : L2);
                uint4 AH = (kx == 0) ? H0 : ((kx == 1) ? H1 : H2);
                const uint4* wt = wq + (ky*3 + kx)*8;
                #pragma unroll
                for (int o = 0; o < 4; o++) {
                    uint4 WL = wt[o*2], WH = wt[o*2 + 1];
                    uint32_t v0 = AL.x ^ WL.x, v1 = AL.y ^ WL.y;
                    uint32_t v2 = AL.z ^ WL.z, v3 = AL.w ^ WL.w;
                    uint32_t v4 = AH.x ^ WH.x, v5 = AH.y ^ WH.y;
                    uint32_t v6 = AH.z ^ WH.z, v7 = AH.w ^ WH.w;
                    uint32_t sA, cA, sB, cB, S, C;
                    FA(v0, v1, v2, sA, cA);
                    FA(v3, v4, v5, sB, cB);
                    FA(sA, sB, v6, S, C);
                    int p1 = __popc(S) + __popc(v7);
                    int p2 = __popc(cA) + __popc(cB) + __popc(C);
                    if (o == 0) { acc1_0 += p1; acc2_0 += p2; }
                    if (o == 1) { acc1_1 += p1; acc2_1 += p2; }
                    if (o == 2) { acc1_2 += p1; acc2_2 += p2; }
                    if (o == 3) { acc1_3 += p1; acc2_3 += p2; }
                }
            }
        }
        const int* adj = s_adj + (g*4)*9 + combo;
        yout[(g*4 + 0)*PIX] = (short)(adj[0]  - 2*(acc1_0 + 2*acc2_0));
        yout[(g*4 + 1)*PIX] = (short)(adj[9]  - 2*(acc1_1 + 2*acc2_1));
        yout[(g*4 + 2)*PIX] = (short)(adj[18] - 2*(acc1_2 + 2*acc2_2));
        yout[(g*4 + 3)*PIX] = (short)(adj[27] - 2*(acc1_3 + 2*acc2_3));
    }
}

// ---------------- per-channel stats -> scale/shift (no atomics) ------------
__global__ void __launch_bounds__(512) chanstats_kernel(int which,
                                                        const float* __restrict__ gamma,
                                                        const float* __restrict__ beta) {
    const int oc = blockIdx.x;
    int s1 = 0, s2 = 0;     // per-thread <=25 short4: s2 <= 531M < 2^31
    for (int i = threadIdx.x; i < NB*196; i += 512) {
        int nn = i / 196, j = i - nn*196;
        short4 v = ((const short4*)(g_y + ((size_t)(nn*CC + oc))*PIX))[j];
        int a = v.x, b = v.y, c = v.z, d = v.w;
        s1 += (a + b) + (c + d);
        s2 += (a*a + b*b) + (c*c + d*d);
    }
    long long l1 = s1, l2 = s2;
    #pragma unroll
    for (int o = 16; o; o >>= 1) {
        l1 += __shfl_down_sync(0xffffffffu, l1, o);
        l2 += __shfl_down_sync(0xffffffffu, l2, o);
    }
    __shared__ long long sh1[16], sh2[16];
    int warp = threadIdx.x >> 5, lane = threadIdx.x & 31;
    if (lane == 0) { sh1[warp] = l1; sh2[warp] = l2; }
    __syncthreads();
    if (threadIdx.x == 0) {
        long long t1 = 0, t2 = 0;
        #pragma unroll
        for (int k = 0; k < 16; k++) { t1 += sh1[k]; t2 += sh2[k]; }
        double m   = (double)t1 / (double)NPIX;
        double ex2 = (double)t2 / (double)NPIX;
        double var = ex2 - m*m;
        double inv = rsqrt(var + 1e-5);
        double gs  = (double)gamma[oc] * inv;
        g_scale[which][oc] = (float)gs;
        g_shift[which][oc] = (float)((double)beta[oc] - m * gs);
    }
}

// ---------------- stage-1 BN + residual + clip, fused sign-pack ------------
// block (h, n); 256 threads = channels. Writes out1 (NCHW) and the packed
// stage-2 sign bits directly (replaces the second pack_sign pass).
__global__ void __launch_bounds__(256) bnres1_pack_kernel(const float* __restrict__ x) {
    __shared__ unsigned char s[CC*WW];
    int h = blockIdx.x, n = blockIdx.y, c = threadIdx.x;
    float sc = g_scale[0][c], sf = g_shift[0][c];
    size_t base = ((size_t)(n*CC + c))*PIX + h*WW;
    const short4* yp = (const short4*)(g_y + base);
    const float4* xp = (const float4*)(x + base);
    float4* op = (float4*)(g_out1 + base);
    #pragma unroll
    for (int q = 0; q < 7; q++) {
        short4 y4 = yp[q];
        float4 x4 = xp[q];
        float4 o;
        o.x = fminf(1.f, fmaxf(-1.f, fmaf((float)y4.x, sc, sf) + x4.x));
        o.y = fminf(1.f, fmaxf(-1.f, fmaf((float)y4.y, sc, sf) + x4.y));
        o.z = fminf(1.f, fmaxf(-1.f, fmaf((float)y4.z, sc, sf) + x4.z));
        o.w = fminf(1.f, fmaxf(-1.f, fmaf((float)y4.w, sc, sf) + x4.w));
        op[q] = o;
        s[c*28 + q*4 + 0] = (o.x > 0.f) ? 1 : 0;
        s[c*28 + q*4 + 1] = (o.y > 0.f) ? 1 : 0;
        s[c*28 + q*4 + 2] = (o.z > 0.f) ? 1 : 0;
        s[c*28 + q*4 + 3] = (o.w > 0.f) ? 1 : 0;
    }
    __syncthreads();
    int warp = c >> 5, lane = c & 31;
    #pragma unroll
    for (int w = 0; w < 28; w++) {
        unsigned pred = s[(warp*32 + lane)*28 + w];
        unsigned word = __ballot_sync(0xffffffffu, pred != 0);
        if (lane == w) g_bits[n*(PIX*CW) + (h*WW + w)*CW + warp] = word;
    }
}

// ---------------- stage-2 BN + residual + clip (vectorized) ----------------
__global__ void __launch_bounds__(256) bnres2_kernel(float* __restrict__ dst_out) {
    int idx4 = blockIdx.x * 256 + threadIdx.x;     // grid = TOT/1024
    int base = idx4 << 2;
    int c = (base / PIX) & (CC - 1);
    float sc = g_scale[1][c], sf = g_shift[1][c];
    short4 yv = ((const short4*)g_y)[idx4];
    float4 rv = ((const float4*)g_out1)[idx4];
    float4 o;
    o.x = fminf(1.0f, fmaxf(-1.0f, fmaf((float)yv.x, sc, sf) + rv.x));
    o.y = fminf(1.0f, fmaxf(-1.0f, fmaf((float)yv.y, sc, sf) + rv.y));
    o.z = fminf(1.0f, fmaxf(-1.0f, fmaf((float)yv.z, sc, sf) + rv.z));
    o.w = fminf(1.0f, fmaxf(-1.0f, fmaf((float)yv.w, sc, sf) + rv.w));
    ((float4*)dst_out)[idx4] = o;
}

// ---------------- launcher -------------------------------------------------
extern "C" void kernel_launch(void* const* d_in, const int* in_sizes, int n_in,
                              void* d_out, int out_size) {
    const float* x      = (const float*)d_in[0];
    const float* w1     = (const float*)d_in[1];
    const float* gamma1 = (const float*)d_in[2];
    const float* beta1  = (const float*)d_in[3];
    const float* w2     = (const float*)d_in[4];
    const float* gamma2 = (const float*)d_in[5];
    const float* beta2  = (const float*)d_in[6];
    float* out = (float*)d_out;

    constexpr int SMEM_BYTES = SMEM_U32 * 4;       // 16,512 B

    pack_w_kernel<<<dim3(CC, 2), dim3(32, 9)>>>(w1, w2);

    // stage 1
    pack_sign_kernel<<<dim3(HH, NB), 256>>>(x);
    conv_kernel<<<dim3(HH/TH, NB, NCH), 128, SMEM_BYTES>>>(0);
    chanstats_kernel<<<CC, 512>>>(0, gamma1, beta1);
    bnres1_pack_kernel<<<dim3(HH, NB), 256>>>(x);   // out1 + stage-2 sign bits

    // stage 2
    conv_kernel<<<dim3(HH/TH, NB, NCH), 128, SMEM_BYTES>>>(1);
    chanstats_kernel<<<CC, 512>>>(1, gamma2, beta2);
    bnres2_kernel<<<TOT/1024, 256>>>(out);
}

// round 14
// speedup vs baseline: 2.5628x; 1.1185x over previous
#include <cuda_runtime.h>
#include <cstdint>

// Problem constants
#define NB   64
#define CC   256
#define HH   28
#define WW   28
#define PIX  (HH*WW)                 // 784
#define NPIX (NB*PIX)                // 50176
#define TOT  (NB*CC*PIX)             // 12,845,056
#define CW   8                       // 256 channels / 32 bits
#define OCCH 32                      // output channels per block
#define NCH  (CC/OCCH)               // 8 chunks
#define NG   (OCCH/4)                // 8 groups of 4 ocs
#define NROW (NB*HH)                 // 1792 global rows
#define QBLK 128                     // pixels per conv block
#define NQB  (NPIX/QBLK)             // 392

// ---------------- scratch (device globals) ---------------------------------
__device__ uint32_t g_bits[NPIX*CW];              // packed signs [q][8]
__device__ uint32_t g_wb[2][CC*72];               // packed weight signs
__device__ int      g_pw[2][CC*9];                // popcount of each weight tap
__device__ short    g_y[2][TOT];                  // integer conv outputs (NCHW)
__device__ long long g_pp1[4][CC], g_pp2[4][CC];  // chanstat partials
__device__ float    g_scale[2][CC], g_shift[2][CC];

// ---------------- pack weights: sign bits + per-tap popcounts -------------
__global__ void pack_w_kernel(const float* __restrict__ w1,
                              const float* __restrict__ w2) {
    int oc    = blockIdx.x;
    int which = blockIdx.y;
    const float* w = which ? w2 : w1;
    int tap  = threadIdx.y;          // 0..8
    int lane = threadIdx.x;          // 0..31
    int pwt = 0;
    #pragma unroll
    for (int j = 0; j < CW; j++) {
        float v = w[oc*2304 + (j*32 + lane)*9 + tap];
        unsigned word = __ballot_sync(0xffffffffu, v > 0.0f);
        if (lane == 0) g_wb[which][oc*72 + tap*8 + j] = word;
        pwt += __popc(word);
    }
    if (lane == 0) g_pw[which][oc*9 + tap] = pwt;
}

// ---------------- pack x signs (stage 1) ------------------------------------
__global__ void pack_sign_kernel(const float* __restrict__ src) {
    __shared__ unsigned char s[CC*WW];      // 7168 sign bytes
    int h = blockIdx.x, n = blockIdx.y;
    int basen = n * (CC*PIX);
    #pragma unroll
    for (int k = 0; k < 28; k++) {
        int e = threadIdx.x + k*256;         // e = c*28 + w
        int c = e / 28, w = e - c*28;
        float v = src[basen + c*PIX + h*WW + w];
        s[e] = (v > 0.0f) ? 1 : 0;
    }
    __syncthreads();
    int warp = threadIdx.x >> 5, lane = threadIdx.x & 31;
    #pragma unroll
    for (int w = 0; w < 28; w++) {
        unsigned pred = s[(warp*32 + lane)*28 + w];
        unsigned word = __ballot_sync(0xffffffffu, pred != 0);
        if (lane == w) g_bits[((n*HH + h)*WW + w)*CW + warp] = word;
    }
}

// ---------------- XNOR conv, flattened-q tiles (all 128 lanes active) ------
// Block = 128 consecutive pixels q. Tile = 8 global rows (R0-1..R0+6) + zero
// row (slot 8); threads at h boundaries redirect invalid ky to the zero row.
// Per (oc,tap): 8 XOR words -> 3 FAs -> 5 popcs (weights 1,1,2,2,2).
#define SMEM_W_U32  (OCCH*72)                 // 2304  [g][tap][o][j]
#define SMEM_A_U32  (9*2*32*4)                // 2304  [rowslot][half][col][k]
#define SMEM_ADJ    (OCCH*9)                  // 288
#define SMEM_U32    (SMEM_W_U32 + SMEM_A_U32 + SMEM_ADJ)

#define FA(x, y, z, s, c)  { s = (x)^(y)^(z); c = ((x)&(y)) | ((z)&((x)|(y))); }

__global__ void __launch_bounds__(128, 6) conv_kernel(int which) {
    extern __shared__ uint32_t sh[];
    uint32_t* s_w  = sh;                              // [g][tap][o][j0..7]
    uint32_t* s_a  = sh + SMEM_W_U32;                 // [slot][half][col][k]
    int*      s_adj = (int*)(sh + SMEM_W_U32 + SMEM_A_U32);

    const int q0  = blockIdx.x * QBLK;
    const int oc0 = blockIdx.y * OCCH;
    const int tid = threadIdx.x;
    const int R0  = q0 / 28;

    const uint32_t* wb = g_wb[which];
    for (int i = tid; i < SMEM_W_U32; i += 128) {
        int j   = i & 7;
        int o   = (i >> 3) & 3;
        int rem = i % 288;
        int tap = rem >> 5;
        int g   = i / 288;
        s_w[i] = wb[(oc0 + g*4 + o)*72 + tap*8 + j];
    }
    // activation tile: slots 0..7 = rows R0-1..R0+6, slot 8 = zeros
    for (int i = tid; i < SMEM_A_U32; i += 128) {
        uint32_t v = 0;
        if (i < 8*2*32*4) {
            int k    = i & 3;
            int col  = (i >> 2) & 31;
            int half = (i >> 7) & 1;
            int t    = i >> 8;
            int Rt   = R0 - 1 + t;
            int wo   = col - 1;
            if (Rt >= 0 && Rt < NROW && wo >= 0 && wo < 28)
                v = g_bits[(Rt*28 + wo)*CW + half*4 + k];
        }
        s_a[i] = v;
    }
    const int* pw = g_pw[which] + oc0*9;
    for (int e = tid; e < SMEM_ADJ; e += 128) {
        int ocl = e / 9, combo = e - ocl*9;
        int rs = combo / 3, cs = combo - rs*3;
        const int* pwo = pw + ocl*9;
        int corr = 0;
        if (rs) { int ir = (rs == 1) ? 0 : 2;
                  corr += pwo[ir*3] + pwo[ir*3+1] + pwo[ir*3+2]; }
        if (cs) { int ic = (cs == 1) ? 0 : 2;
                  corr += pwo[ic] + pwo[3+ic] + pwo[6+ic]; }
        if (rs && cs) { int ir = (rs == 1) ? 0 : 2, ic = (cs == 1) ? 0 : 2;
                        corr -= pwo[ir*3 + ic]; }
        int nv = (rs ? 2 : 3) * (cs ? 2 : 3);
        s_adj[e] = CC*nv + 2*corr;
    }
    __syncthreads();

    const int q = q0 + tid;             // all lanes active
    const int R = q / 28;
    const int w = q - R*28;
    const int h = R % 28;
    const int n = R / 28;
    const int pos = q - n*PIX;

    const int rs = (h == 0) ? 1 : ((h == HH-1) ? 2 : 0);
    const int cs = (w == 0) ? 1 : ((w == WW-1) ? 2 : 0);
    const int combo = rs*3 + cs;

    const int bt = R - R0;              // 0..5
    const int t0 = (h > 0)    ? bt     : 8;   // ky=0 row slot
    const int t1 = bt + 1;                    // ky=1
    const int t2 = (h < HH-1) ? bt + 2 : 8;   // ky=2

    short* yout = g_y[which] + ((size_t)n*CC + oc0)*PIX + pos;  // + ocl*PIX

    for (int g = 0; g < NG; g++) {
        int acc1_0 = 0, acc1_1 = 0, acc1_2 = 0, acc1_3 = 0;   // weight-1 popcs
        int acc2_0 = 0, acc2_1 = 0, acc2_2 = 0, acc2_3 = 0;   // weight-2 popcs
        const uint4* wq = (const uint4*)s_w + g*72;            // [tap][o][lo/hi]
        #pragma unroll
        for (int ky = 0; ky < 3; ky++) {
            const int tk = (ky == 0) ? t0 : ((ky == 1) ? t1 : t2);
            const uint4* apL = (const uint4*)s_a + ((tk*2 + 0)*32 + w);
            const uint4* apH = (const uint4*)s_a + ((tk*2 + 1)*32 + w);
            uint4 L0 = apL[0], L1 = apL[1], L2 = apL[2];
            uint4 H0 = apH[0], H1 = apH[1], H2 = apH[2];
            #pragma unroll
            for (int kx = 0; kx < 3; kx++) {
                uint4 AL = (kx == 0) ? L0 : ((kx == 1) ? L1 : L2);
                uint4 AH = (kx == 0) ? H0 : ((kx == 1) ? H1 : H2);
                const uint4* wt = wq + (ky*3 + kx)*8;
                #pragma unroll
                for (int o = 0; o < 4; o++) {
                    uint4 WL = wt[o*2], WH = wt[o*2 + 1];
                    uint32_t v0 = AL.x ^ WL.x, v1 = AL.y ^ WL.y;
                    uint32_t v2 = AL.z ^ WL.z, v3 = AL.w ^ WL.w;
                    uint32_t v4 = AH.x ^ WH.x, v5 = AH.y ^ WH.y;
                    uint32_t v6 = AH.z ^ WH.z, v7 = AH.w ^ WH.w;
                    uint32_t sA, cA, sB, cB, S, C;
                    FA(v0, v1, v2, sA, cA);
                    FA(v3, v4, v5, sB, cB);
                    FA(sA, sB, v6, S, C);
                    int p1 = __popc(S) + __popc(v7);
                    int p2 = __popc(cA) + __popc(cB) + __popc(C);
                    if (o == 0) { acc1_0 += p1; acc2_0 += p2; }
                    if (o == 1) { acc1_1 += p1; acc2_1 += p2; }
                    if (o == 2) { acc1_2 += p1; acc2_2 += p2; }
                    if (o == 3) { acc1_3 += p1; acc2_3 += p2; }
                }
            }
        }
        const int* adj = s_adj + (g*4)*9 + combo;
        yout[(g*4 + 0)*PIX] = (short)(adj[0]  - 2*(acc1_0 + 2*acc2_0));
        yout[(g*4 + 1)*PIX] = (short)(adj[9]  - 2*(acc1_1 + 2*acc2_1));
        yout[(g*4 + 2)*PIX] = (short)(adj[18] - 2*(acc1_2 + 2*acc2_2));
        yout[(g*4 + 3)*PIX] = (short)(adj[27] - 2*(acc1_3 + 2*acc2_3));
    }
}

// ---------------- per-channel stat partials (4 batch slices) ---------------
__global__ void __launch_bounds__(512) chanstats_kernel(int which) {
    const int oc = blockIdx.x, sl = blockIdx.y;     // slice = 16 images
    int s1 = 0, s2 = 0;     // <=7 short4/thread: s2 <= 149M < 2^31
    for (int i = threadIdx.x; i < 16*196; i += 512) {
        int nn = sl*16 + i/196, j = i % 196;
        short4 v = ((const short4*)(g_y[which] + ((size_t)(nn*CC + oc))*PIX))[j];
        int a = v.x, b = v.y, c = v.z, d = v.w;
        s1 += (a + b) + (c + d);
        s2 += (a*a + b*b) + (c*c + d*d);
    }
    long long l1 = s1, l2 = s2;
    #pragma unroll
    for (int o = 16; o; o >>= 1) {
        l1 += __shfl_down_sync(0xffffffffu, l1, o);
        l2 += __shfl_down_sync(0xffffffffu, l2, o);
    }
    __shared__ long long sh1[16], sh2[16];
    int warp = threadIdx.x >> 5, lane = threadIdx.x & 31;
    if (lane == 0) { sh1[warp] = l1; sh2[warp] = l2; }
    __syncthreads();
    if (threadIdx.x == 0) {
        long long t1 = 0, t2 = 0;
        #pragma unroll
        for (int k = 0; k < 16; k++) { t1 += sh1[k]; t2 += sh2[k]; }
        g_pp1[sl][oc] = t1;  g_pp2[sl][oc] = t2;
    }
}

// ---------------- finalize BN coefficients ---------------------------------
__global__ void finalize_kernel(int which, const float* __restrict__ gamma,
                                const float* __restrict__ beta) {
    int oc = threadIdx.x;                      // 256 threads
    long long t1 = g_pp1[0][oc] + g_pp1[1][oc] + g_pp1[2][oc] + g_pp1[3][oc];
    long long t2 = g_pp2[0][oc] + g_pp2[1][oc] + g_pp2[2][oc] + g_pp2[3][oc];
    double m   = (double)t1 / (double)NPIX;
    double ex2 = (double)t2 / (double)NPIX;
    double inv = rsqrt(ex2 - m*m + 1e-5);
    double gs  = (double)gamma[oc] * inv;
    g_scale[which][oc] = (float)gs;
    g_shift[which][oc] = (float)((double)beta[oc] - m * gs);
}

// ---------------- stage-1 BN+res+clip -> stage-2 sign bits only ------------
// pack_sign-style indexing (proven fast); out1 is NOT materialized — bnres2
// recomputes it bit-identically from (y1, x).
__global__ void __launch_bounds__(256) bnres1_pack_kernel(const float* __restrict__ x) {
    __shared__ unsigned char s[CC*WW];
    __shared__ float ssc[CC], ssf[CC];
    int h = blockIdx.x, n = blockIdx.y, tid = threadIdx.x;
    ssc[tid] = g_scale[0][tid];
    ssf[tid] = g_shift[0][tid];
    __syncthreads();
    int basen = n * (CC*PIX);
    const short* yp = g_y[0];
    #pragma unroll
    for (int k = 0; k < 28; k++) {
        int e = tid + k*256;                 // e = c*28 + w
        int c = e / 28, w = e - c*28;
        int idx = basen + c*PIX + h*WW + w;
        float o = fmaf((float)yp[idx], ssc[c], ssf[c]) + x[idx];
        o = fminf(1.0f, fmaxf(-1.0f, o));
        s[e] = (o > 0.0f) ? 1 : 0;
    }
    __syncthreads();
    int warp = tid >> 5, lane = tid & 31;
    #pragma unroll
    for (int w = 0; w < 28; w++) {
        unsigned pred = s[(warp*32 + lane)*28 + w];
        unsigned word = __ballot_sync(0xffffffffu, pred != 0);
        if (lane == w) g_bits[((n*HH + h)*WW + w)*CW + warp] = word;
    }
}

// ---------------- stage-2: recompute o1, BN2 + res + clip (coalesced) ------
__global__ void __launch_bounds__(256) bnres2_kernel(const float* __restrict__ x,
                                                     float* __restrict__ dst_out) {
    int idx4 = blockIdx.x * 256 + threadIdx.x;     // grid = TOT/1024
    int base = idx4 << 2;
    int c = (base / PIX) & (CC - 1);
    float s0 = g_scale[0][c], f0 = g_shift[0][c];
    float s1 = g_scale[1][c], f1 = g_shift[1][c];
    short4 y1 = ((const short4*)g_y[0])[idx4];
    short4 y2 = ((const short4*)g_y[1])[idx4];
    float4 xv = ((const float4*)x)[idx4];
    float4 o;
    float o1;
    o1  = fminf(1.0f, fmaxf(-1.0f, fmaf((float)y1.x, s0, f0) + xv.x));
    o.x = fminf(1.0f, fmaxf(-1.0f, fmaf((float)y2.x, s1, f1) + o1));
    o1  = fminf(1.0f, fmaxf(-1.0f, fmaf((float)y1.y, s0, f0) + xv.y));
    o.y = fminf(1.0f, fmaxf(-1.0f, fmaf((float)y2.y, s1, f1) + o1));
    o1  = fminf(1.0f, fmaxf(-1.0f, fmaf((float)y1.z, s0, f0) + xv.z));
    o.z = fminf(1.0f, fmaxf(-1.0f, fmaf((float)y2.z, s1, f1) + o1));
    o1  = fminf(1.0f, fmaxf(-1.0f, fmaf((float)y1.w, s0, f0) + xv.w));
    o.w = fminf(1.0f, fmaxf(-1.0f, fmaf((float)y2.w, s1, f1) + o1));
    ((float4*)dst_out)[idx4] = o;
}

// ---------------- launcher -------------------------------------------------
extern "C" void kernel_launch(void* const* d_in, const int* in_sizes, int n_in,
                              void* d_out, int out_size) {
    const float* x      = (const float*)d_in[0];
    const float* w1     = (const float*)d_in[1];
    const float* gamma1 = (const float*)d_in[2];
    const float* beta1  = (const float*)d_in[3];
    const float* w2     = (const float*)d_in[4];
    const float* gamma2 = (const float*)d_in[5];
    const float* beta2  = (const float*)d_in[6];
    float* out = (float*)d_out;

    constexpr int SMEM_BYTES = SMEM_U32 * 4;       // 19,584 B

    pack_w_kernel<<<dim3(CC, 2), dim3(32, 9)>>>(w1, w2);

    // stage 1
    pack_sign_kernel<<<dim3(HH, NB), 256>>>(x);
    conv_kernel<<<dim3(NQB, NCH), 128, SMEM_BYTES>>>(0);
    chanstats_kernel<<<dim3(CC, 4), 512>>>(0);
    finalize_kernel<<<1, 256>>>(0, gamma1, beta1);
    bnres1_pack_kernel<<<dim3(HH, NB), 256>>>(x);   // stage-2 sign bits only

    // stage 2
    conv_kernel<<<dim3(NQB, NCH), 128, SMEM_BYTES>>>(1);
    chanstats_kernel<<<dim3(CC, 4), 512>>>(1);
    finalize_kernel<<<1, 256>>>(1, gamma2, beta2);
    bnres2_kernel<<<TOT/1024, 256>>>(x, out);
}